// round 12
// baseline (speedup 1.0000x reference)
#include <cuda_runtime.h>
#include <cuda_bf16.h>
#include <cstdint>

// EDMLoss = mean((Xhat-X)^2) + 0.25*memloss - 0.1*mean(Dhat)
// memloss = 2*(sum||h||^2 + sum_row min_k(||m_k||^2 - 2 h.m_k)) / (B*D*T)
// GEMM [32768x256]@[256x512] via mma.sync bf16 on ALL 148 SMs:
// 1024 units (128 rows x 128 cols), static contiguous ranges over 148
// persistent CTAs. Row-mins merged via global atomicMin (order-preserving
// keys); device-wide ticket barrier; phase 2 sums mins + rec + dhat.
// R12 fix: phase-2 smem scratch no longer aliases (dmin/srec/sdh disjoint).

namespace {
constexpr int Bn = 64, Dn = 256, Tn = 512, Kn = 512;
constexpr int N_REC  = 64 * 8 * 512;
constexpr int N_DHAT = 64 * 512;
constexpr int NCTA   = 148;
constexpr int NUNIT  = 1024;                    // (32768/128) * (512/128)
constexpr int NROWS  = 32768;
constexpr unsigned INIT_KEY = 0xFF800000u;      // encode(+inf)

constexpr uint32_t AP    = 272;                 // A pitch: 128 bf16 + 16B pad
constexpr uint32_t BP    = 272;                 // B pitch: 128 bf16 + 16B pad
constexpr uint32_t SA    = 0;                   // A: 256*272 = 69632
constexpr uint32_t SB0   = 69632;               // B buf0: 256*272
constexpr uint32_t SB1   = 139264;              // B buf1
constexpr uint32_t SMNS  = 208896;              // 512 f32 ||m||^2
constexpr uint32_t SRED  = 210944;              // 8 doubles | +64: 8 f32 | +96: 8 f32
constexpr uint32_t SMEMT = 211072;
}

__device__ double g_acc[4];      // 0 rec, 1 minscore, 2 dhat, 3 sum H^2 (zero-invariant)
__device__ unsigned g_ticket, g_ticket2;
__device__ float  g_mnorm[Kn];
__device__ unsigned g_rmin[NROWS];              // INIT_KEY invariant between runs
__device__ __align__(16) __nv_bfloat16 g_Mc[(size_t)Dn * Kn];

__device__ __forceinline__ uint32_t smem_u32(const void* p) {
    uint32_t a;
    asm("{ .reg .u64 t; cvta.to.shared.u64 t, %1; cvt.u32.u64 %0, t; }" : "=r"(a) : "l"(p));
    return a;
}
__device__ __forceinline__ void ldsm4t(uint32_t* r, uint32_t addr) {
    asm volatile("ldmatrix.sync.aligned.m8n8.x4.trans.shared.b16 {%0,%1,%2,%3}, [%4];"
                 : "=r"(r[0]), "=r"(r[1]), "=r"(r[2]), "=r"(r[3]) : "r"(addr));
}
__device__ __forceinline__ void mma16816(float* c, const uint32_t* a, const uint32_t* b) {
    asm volatile("mma.sync.aligned.m16n8k16.row.col.f32.bf16.bf16.f32 "
                 "{%0,%1,%2,%3}, {%4,%5,%6,%7}, {%8,%9}, {%0,%1,%2,%3};"
                 : "+f"(c[0]), "+f"(c[1]), "+f"(c[2]), "+f"(c[3])
                 : "r"(a[0]), "r"(a[1]), "r"(a[2]), "r"(a[3]), "r"(b[0]), "r"(b[1]));
}
__device__ __forceinline__ unsigned enc(float f) {
    unsigned u = __float_as_uint(f);
    return (u & 0x80000000u) ? ~u : (u | 0x80000000u);
}
__device__ __forceinline__ float dec(unsigned k) {
    unsigned u = (k & 0x80000000u) ? (k & 0x7FFFFFFFu) : ~k;
    return __uint_as_float(u);
}

// ---- prep: M -> bf16 + ||m||^2 (16 blocks x 32 k-cols) + g_rmin init ----
__global__ __launch_bounds__(256) void k_prep(const float* __restrict__ M) {
    __shared__ float part[8][32];
    const int kl = threadIdx.x & 31;
    const int dg = threadIdx.x >> 5;
    const int k  = blockIdx.x * 32 + kl;
    float s = 0.f;
    #pragma unroll 8
    for (int i = 0; i < 32; ++i) {
        int d = dg * 32 + i;
        float v = M[(size_t)d * Kn + k];
        g_Mc[(size_t)d * Kn + k] = __float2bfloat16(v);
        s = fmaf(v, v, s);
    }
    part[dg][kl] = s;
    #pragma unroll
    for (int i = 0; i < 8; ++i)
        g_rmin[blockIdx.x * 2048 + threadIdx.x + i * 256] = INIT_KEY;
    __syncthreads();
    if (dg == 0) {
        float t = 0.f;
        #pragma unroll
        for (int i = 0; i < 8; ++i) t += part[i][kl];
        g_mnorm[k] = t;
    }
}

// ---- persistent GEMM on all 148 SMs ----
__global__ __launch_bounds__(256, 1) void k_mma(const float* __restrict__ H,
                                                const float* __restrict__ Xhat,
                                                const float* __restrict__ X,
                                                const float* __restrict__ Dh,
                                                float* out) {
    extern __shared__ char sm[];
    const uint32_t sb = smem_u32(sm);
    const int tid = threadIdx.x, w = tid >> 5, ln = tid & 31;
    const int bid = blockIdx.x;

    ((float*)(sm + SMNS))[tid]       = g_mnorm[tid];
    ((float*)(sm + SMNS))[tid + 256] = g_mnorm[tid + 256];

    const int u_lo = (int)(((long)bid * NUNIT) / NCTA);
    const int u_hi = (int)(((long)(bid + 1) * NUNIT) / NCTA);
    const int nu   = u_hi - u_lo;

    const size_t gmc = __cvta_generic_to_global((const void*)g_Mc);
    auto cp_chunk = [&](int u, uint32_t dstoff) {       // B: 256 d x 128 cols bf16
        int cc = u & 3;
        #pragma unroll
        for (int i = 0; i < 16; ++i) {
            int v = tid + 256 * i;                      // 0..4095 16B units
            int d = v >> 4, seg = v & 15;
            uint32_t dst = sb + dstoff + d * BP + seg * 16;
            size_t   src = gmc + (size_t)d * 1024 + (size_t)cc * 256 + seg * 16;
            asm volatile("cp.async.cg.shared.global [%0], [%1], 16;" :: "r"(dst), "l"(src));
        }
        asm volatile("cp.async.commit_group;" ::: "memory");
    };
    cp_chunk(u_lo, SB0);
    if (nu > 1) cp_chunk(u_lo + 1, SB1);

    const int wm = (w & 3) * 32;          // warp rows base (128-row unit)
    const int wn = (w >> 2) * 64;         // warp cols base (128-col unit)
    const int s1 = ((ln >> 3) & 1) * 8;
    const int s2 = (ln >> 4) * 8;
    const int r8 = ln & 7;
    const float* mns = (const float*)(sm + SMNS);

    int staged_tile = -1;

    for (int j = 0; j < nu; ++j) {
        const int u = u_lo + j;
        const int tile = u >> 2, cc = u & 3;
        const int row0 = tile * 128;

        if (j + 1 < nu) asm volatile("cp.async.wait_group 1;" ::: "memory");
        else            asm volatile("cp.async.wait_group 0;" ::: "memory");
        __syncthreads();

        if (tile != staged_tile) {
            // Stage A: H[b][d][t0..t0+127] -> bf16 smem [d][t]; sq only on cc==0.
            const int b = row0 >> 9, t0 = row0 & 511;
            const float* Hp = H + (size_t)b * Dn * Tn + t0;
            float sq = 0.f;
            #pragma unroll
            for (int i = 0; i < 32; ++i) {
                int d = i * 8 + w;
                float4 v = *(const float4*)(Hp + (size_t)d * Tn + ln * 4);
                if (cc == 0)
                    sq = fmaf(v.x, v.x, fmaf(v.y, v.y, fmaf(v.z, v.z, fmaf(v.w, v.w, sq))));
                __nv_bfloat162 p0 = __floats2bfloat162_rn(v.x, v.y);
                __nv_bfloat162 p1 = __floats2bfloat162_rn(v.z, v.w);
                uint32_t a = sb + SA + d * AP + ln * 8;
                asm volatile("st.shared.v2.b32 [%0], {%1,%2};"
                             :: "r"(a), "r"(*(uint32_t*)&p0), "r"(*(uint32_t*)&p1) : "memory");
            }
            staged_tile = tile;
            if (cc == 0) {
                #pragma unroll
                for (int o = 16; o; o >>= 1) sq += __shfl_down_sync(0xffffffffu, sq, o);
                if (!ln) ((float*)(sm + SRED + 64))[w] = sq;
            }
            __syncthreads();
            if (cc == 0 && tid == 0) {
                const float* ws = (const float*)(sm + SRED + 64);
                double hs = 0.0;
                #pragma unroll
                for (int i = 0; i < 8; ++i) hs += (double)ws[i];
                atomicAdd(&g_acc[3], hs);
            }
        }

        const uint32_t bb = sb + ((j & 1) ? SB1 : SB0);

        float acc[2][8][4];
        #pragma unroll
        for (int mf = 0; mf < 2; ++mf)
            #pragma unroll
            for (int nf = 0; nf < 8; ++nf)
                #pragma unroll
                for (int q = 0; q < 4; ++q) acc[mf][nf][q] = 0.f;

        #pragma unroll
        for (int ks = 0; ks < 16; ++ks) {
            const int d0 = ks * 16;
            uint32_t af[2][4], bf[4][4];
            #pragma unroll
            for (int np = 0; np < 4; ++np)
                ldsm4t(bf[np], bb + (d0 + s1 + r8) * BP + (wn + np * 16 + s2) * 2);
            #pragma unroll
            for (int mf = 0; mf < 2; ++mf)
                ldsm4t(af[mf], sb + SA + (d0 + s2 + r8) * AP + (wm + mf * 16 + s1) * 2);
            #pragma unroll
            for (int mf = 0; mf < 2; ++mf)
                #pragma unroll
                for (int nf = 0; nf < 8; ++nf)
                    mma16816(acc[mf][nf], af[mf], &bf[nf >> 1][(nf & 1) * 2]);
        }

        // release B buffer, prefetch unit j+2 into it
        __syncthreads();
        if (j + 2 < nu) cp_chunk(u + 2, (j & 1) ? SB1 : SB0);

        // epilogue: score = ||m||^2 - 2*dot -> per-row min -> global atomicMin
        float rm[4] = {3.4e38f, 3.4e38f, 3.4e38f, 3.4e38f};
        const int cb = cc * 128 + wn + 2 * (ln & 3);
        #pragma unroll
        for (int nf = 0; nf < 8; ++nf) {
            float m0 = mns[cb + nf * 8], m1 = mns[cb + nf * 8 + 1];
            rm[0] = fminf(rm[0], fminf(fmaf(-2.f, acc[0][nf][0], m0), fmaf(-2.f, acc[0][nf][1], m1)));
            rm[1] = fminf(rm[1], fminf(fmaf(-2.f, acc[0][nf][2], m0), fmaf(-2.f, acc[0][nf][3], m1)));
            rm[2] = fminf(rm[2], fminf(fmaf(-2.f, acc[1][nf][0], m0), fmaf(-2.f, acc[1][nf][1], m1)));
            rm[3] = fminf(rm[3], fminf(fmaf(-2.f, acc[1][nf][2], m0), fmaf(-2.f, acc[1][nf][3], m1)));
        }
        #pragma unroll
        for (int o = 1; o < 4; o <<= 1) {
            #pragma unroll
            for (int i = 0; i < 4; ++i) rm[i] = fminf(rm[i], __shfl_xor_sync(0xffffffffu, rm[i], o));
        }
        if ((ln & 3) == 0) {
            int r = row0 + wm + (ln >> 2);
            atomicMin(&g_rmin[r],      enc(rm[0]));
            atomicMin(&g_rmin[r + 8],  enc(rm[1]));
            atomicMin(&g_rmin[r + 16], enc(rm[2]));
            atomicMin(&g_rmin[r + 24], enc(rm[3]));
        }
    }

    // ---- device-wide barrier (all 148 CTAs wave-1 resident at 1 CTA/SM) ----
    __syncthreads();
    if (tid == 0) {
        __threadfence();
        atomicAdd(&g_ticket, 1u);
        while (*((volatile unsigned*)&g_ticket) < (unsigned)NCTA) __nanosleep(128);
    }
    __syncthreads();
    __threadfence();

    // ---- phase 2: row-min sum (+reset), rec, dhat ----
    {
        const int r_lo = (int)(((long)bid * NROWS) / NCTA);
        const int r_hi = (int)(((long)(bid + 1) * NROWS) / NCTA);
        double smin = 0.0;
        for (int r = r_lo + tid; r < r_hi; r += 256) {
            smin += (double)dec(g_rmin[r]);
            g_rmin[r] = INIT_KEY;                       // restore invariant
        }
        float srec = 0.f;
        for (int i = bid * 256 + tid; i < N_REC; i += NCTA * 256) {
            float d = Xhat[i] - X[i]; srec = fmaf(d, d, srec);
        }
        float sdh = 0.f;
        for (int i = bid * 256 + tid; i < N_DHAT; i += NCTA * 256) sdh += Dh[i];

        #pragma unroll
        for (int o = 16; o; o >>= 1) {
            smin += __shfl_down_sync(0xffffffffu, smin, o);
            srec += __shfl_down_sync(0xffffffffu, srec, o);
            sdh  += __shfl_down_sync(0xffffffffu, sdh, o);
        }
        double* dmin = (double*)(sm + SRED);            // 8 doubles: SRED..SRED+64
        float*  frec = (float*)(sm + SRED + 64);        // 8 floats : +64..+96
        float*  fdh  = (float*)(sm + SRED + 96);        // 8 floats : +96..+128
        if (!ln) { dmin[w] = smin; frec[w] = srec; fdh[w] = sdh; }
        __syncthreads();
        if (tid == 0) {
            double tm = 0.0; float tr = 0.f, td = 0.f;
            #pragma unroll
            for (int i = 0; i < 8; ++i) { tm += dmin[i]; tr += frec[i]; td += fdh[i]; }
            atomicAdd(&g_acc[1], tm);
            atomicAdd(&g_acc[0], (double)tr);
            atomicAdd(&g_acc[2], (double)td);
        }
    }

    // ---- finalize ----
    if (tid == 0) {
        __threadfence();
        unsigned old = atomicAdd(&g_ticket2, 1u);
        if (old == (unsigned)NCTA - 1) {
            __threadfence();
            double a0 = *(volatile double*)&g_acc[0];
            double a1 = *(volatile double*)&g_acc[1];
            double a2 = *(volatile double*)&g_acc[2];
            double a3 = *(volatile double*)&g_acc[3];
            double mem = 2.0 * (a3 + a1) / (double)((size_t)Bn * Dn * Tn);
            out[0] = (float)(a0 / (double)N_REC + 0.25 * mem - 0.1 * a2 / (double)N_DHAT);
            g_acc[0] = 0.0; g_acc[1] = 0.0; g_acc[2] = 0.0; g_acc[3] = 0.0;
            g_ticket = 0u; g_ticket2 = 0u;
            __threadfence();
        }
    }
}

extern "C" void kernel_launch(void* const* d_in, const int* in_sizes, int n_in,
                              void* d_out, int out_size) {
    (void)in_sizes; (void)n_in; (void)out_size;
    const float* Xhat = (const float*)d_in[0];
    const float* X    = (const float*)d_in[1];
    const float* H    = (const float*)d_in[2];
    const float* M    = (const float*)d_in[3];
    const float* Dh   = (const float*)d_in[4];

    cudaFuncSetAttribute(k_mma, cudaFuncAttributeMaxDynamicSharedMemorySize, SMEMT);

    k_prep<<<16, 256>>>(M);
    k_mma<<<NCTA, 256, SMEMT>>>(H, Xhat, X, Dh, (float*)d_out);
}

// round 13
// speedup vs baseline: 1.2465x; 1.2465x over previous
#include <cuda_runtime.h>
#include <cuda_bf16.h>
#include <cstdint>

// EDMLoss = mean((Xhat-X)^2) + 0.25*memloss - 0.1*mean(Dhat)
// memloss = 2*(sum||h||^2 + sum_row min_k(||m_k||^2 - 2 h.m_k)) / (B*D*T)
// GEMM [32768x256]@[256x512] via mma.sync bf16 (legacy-path ceiling ~512 MAC/cyc/SM).
// R10 structure (best measured) + single-barrier-per-chunk pipeline:
//   k_prep: M->bf16 + ||m||^2 (16 blocks).
//   k_mma : 128 GEMM CTAs (256 rows x 512 cols) + 20 reduction CTAs; ticket finalize.

namespace {
constexpr int Bn = 64, Dn = 256, Tn = 512, Kn = 512;
constexpr int N_REC  = 64 * 8 * 512;
constexpr int N_DHAT = 64 * 512;

constexpr uint32_t AP    = 528;                 // A pitch bytes (256 bf16 + 16 pad)
constexpr uint32_t BP    = 144;                 // B pitch bytes (64 bf16 + 16 pad)
constexpr uint32_t SA    = 0;                   // A: 256*528 = 135168
constexpr uint32_t SB0   = 135168;              // B buf0: 256*144 = 36864
constexpr uint32_t SB1   = 172032;              // B buf1
constexpr uint32_t SMNS  = 208896;              // 512 f32 ||m||^2
constexpr uint32_t SRMIN = 210944;              // 2 groups * 256 f32 row mins
constexpr uint32_t SRED  = 212992;              // 8 f32 | 8 doubles at +64
constexpr uint32_t SMEMT = 213120;
}

__device__ double g_acc[4];      // 0 rec, 1 minscore, 2 dhat, 3 sum H^2 (zero-invariant)
__device__ unsigned g_ticket;
__device__ float  g_mnorm[Kn];
__device__ __align__(16) __nv_bfloat16 g_Mc[(size_t)Dn * Kn];

__device__ __forceinline__ uint32_t smem_u32(const void* p) {
    uint32_t a;
    asm("{ .reg .u64 t; cvta.to.shared.u64 t, %1; cvt.u32.u64 %0, t; }" : "=r"(a) : "l"(p));
    return a;
}
__device__ __forceinline__ void ldsm4t(uint32_t* r, uint32_t addr) {
    asm volatile("ldmatrix.sync.aligned.m8n8.x4.trans.shared.b16 {%0,%1,%2,%3}, [%4];"
                 : "=r"(r[0]), "=r"(r[1]), "=r"(r[2]), "=r"(r[3]) : "r"(addr));
}
__device__ __forceinline__ void mma16816(float* c, const uint32_t* a, const uint32_t* b) {
    asm volatile("mma.sync.aligned.m16n8k16.row.col.f32.bf16.bf16.f32 "
                 "{%0,%1,%2,%3}, {%4,%5,%6,%7}, {%8,%9}, {%0,%1,%2,%3};"
                 : "+f"(c[0]), "+f"(c[1]), "+f"(c[2]), "+f"(c[3])
                 : "r"(a[0]), "r"(a[1]), "r"(a[2]), "r"(a[3]), "r"(b[0]), "r"(b[1]));
}

// ---- prep: M -> bf16 + ||m||^2, 16 blocks x 32 k-cols ----
__global__ __launch_bounds__(256) void k_prep(const float* __restrict__ M) {
    __shared__ float part[8][32];
    const int kl = threadIdx.x & 31;
    const int dg = threadIdx.x >> 5;
    const int k  = blockIdx.x * 32 + kl;
    float s = 0.f;
    #pragma unroll 8
    for (int i = 0; i < 32; ++i) {
        int d = dg * 32 + i;
        float v = M[(size_t)d * Kn + k];
        g_Mc[(size_t)d * Kn + k] = __float2bfloat16(v);
        s = fmaf(v, v, s);
    }
    part[dg][kl] = s;
    __syncthreads();
    if (dg == 0) {
        float t = 0.f;
        #pragma unroll
        for (int i = 0; i < 8; ++i) t += part[i][kl];
        g_mnorm[k] = t;
    }
}

// ---- main: 128 GEMM CTAs + 20 reduction CTAs, shared ticket ----
__global__ __launch_bounds__(256, 1) void k_mma(const float* __restrict__ H,
                                                const float* __restrict__ Xhat,
                                                const float* __restrict__ X,
                                                const float* __restrict__ Dh,
                                                float* out) {
    extern __shared__ char sm[];
    const uint32_t sb = smem_u32(sm);
    const int tid = threadIdx.x, w = tid >> 5, ln = tid & 31;

    if (blockIdx.x >= 128) {
        // -------- reduction CTAs on otherwise-idle SMs --------
        int which, n, b0, nb;
        const float* a; const float* bp;
        if (blockIdx.x < 146) { which = 0; a = Xhat; bp = X; n = N_REC;  b0 = 128; nb = 18; }
        else                  { which = 2; a = Dh;   bp = 0; n = N_DHAT; b0 = 146; nb = 2;  }
        float s = 0.f;
        for (int i = ((int)blockIdx.x - b0) * 256 + tid; i < n; i += nb * 256) {
            if (which == 0) { float d = a[i] - bp[i]; s = fmaf(d, d, s); }
            else            { s += a[i]; }
        }
        #pragma unroll
        for (int o = 16; o; o >>= 1) s += __shfl_down_sync(0xffffffffu, s, o);
        float* ws = (float*)(sm + SRED);
        if (!ln) ws[w] = s;
        __syncthreads();
        if (tid == 0) {
            float t = 0.f;
            #pragma unroll
            for (int i = 0; i < 8; ++i) t += ws[i];
            atomicAdd(&g_acc[which], (double)t);
        }
    } else {
        // -------- GEMM CTA: 256 rows x 512 cols --------
        const int row0 = blockIdx.x * 256;
        const int b = row0 >> 9, t0 = row0 & 511;          // t0 in {0, 256}

        ((float*)(sm + SMNS))[tid]       = g_mnorm[tid];
        ((float*)(sm + SMNS))[tid + 256] = g_mnorm[tid + 256];

        const size_t gmc = __cvta_generic_to_global((const void*)g_Mc);
        auto cp_chunk = [&](int c, uint32_t dstoff) {       // 64-col chunk: 256 rows * 128B
            #pragma unroll
            for (int i = 0; i < 8; ++i) {
                int u = tid + 256 * i;                      // 0..2047 16B units
                int d = u >> 3, seg = u & 7;
                uint32_t dst = sb + dstoff + d * BP + seg * 16;
                size_t   src = gmc + (size_t)d * 1024 + (size_t)c * 128 + seg * 16;
                asm volatile("cp.async.cg.shared.global [%0], [%1], 16;" :: "r"(dst), "l"(src));
            }
            asm volatile("cp.async.commit_group;" ::: "memory");
        };
        cp_chunk(0, SB0);
        cp_chunk(1, SB1);

        // Stage A: H[b][d][t0..t0+255] fp32 -> bf16 smem [d][t]; accumulate sum(H^2).
        float sq = 0.f;
        const float* Hp = H + (size_t)b * Dn * Tn + t0;
        #pragma unroll
        for (int i = 0; i < 64; ++i) {
            int u = tid + 256 * i;                 // 0..16383 float4 units
            int d = u >> 6, seg = u & 63;
            float4 v = *(const float4*)(Hp + (size_t)d * Tn + seg * 4);
            sq = fmaf(v.x, v.x, fmaf(v.y, v.y, fmaf(v.z, v.z, fmaf(v.w, v.w, sq))));
            __nv_bfloat162 p0 = __floats2bfloat162_rn(v.x, v.y);
            __nv_bfloat162 p1 = __floats2bfloat162_rn(v.z, v.w);
            uint32_t a = sb + SA + d * AP + seg * 8;
            asm volatile("st.shared.v2.b32 [%0], {%1,%2};"
                         :: "r"(a), "r"(*(uint32_t*)&p0), "r"(*(uint32_t*)&p1) : "memory");
        }
        #pragma unroll
        for (int o = 16; o; o >>= 1) sq += __shfl_down_sync(0xffffffffu, sq, o);
        if (!ln) ((float*)(sm + SRED))[w] = sq;

        // 8 warps: 4 (m) x 2 (n). Warp tile per chunk: 64 rows x 32 cols.
        const int wm  = (w & 3) * 64;
        const int wn  = (w >> 2) * 32;
        const int s1  = ((ln >> 3) & 1) * 8;
        const int s2  = (ln >> 4) * 8;
        const int r8  = ln & 7;
        const float* mns = (const float*)(sm + SMNS);

        float rm[8];
        #pragma unroll
        for (int i = 0; i < 8; ++i) rm[i] = 3.4e38f;

        // Single barrier per chunk: at iter c the sync proves chunk c arrived
        // AND all warps finished chunk c-1 -> buffer (c+1)&1 is free; prefetch
        // c+1 immediately, then compute c on top of the in-flight load.
        for (int c = 0; c < 8; ++c) {
            if (c == 0) asm volatile("cp.async.wait_group 1;" ::: "memory");
            else        asm volatile("cp.async.wait_group 0;" ::: "memory");
            __syncthreads();
            if (c >= 1 && c + 1 < 8) cp_chunk(c + 1, ((c + 1) & 1) ? SB1 : SB0);
            const uint32_t bb = sb + ((c & 1) ? SB1 : SB0);

            float acc[4][4][4];
            #pragma unroll
            for (int mf = 0; mf < 4; ++mf)
                #pragma unroll
                for (int nf = 0; nf < 4; ++nf)
                    #pragma unroll
                    for (int j = 0; j < 4; ++j) acc[mf][nf][j] = 0.f;

            #pragma unroll
            for (int ks = 0; ks < 16; ++ks) {
                const int d0 = ks * 16;
                uint32_t af[4][4], bf[2][4];
                #pragma unroll
                for (int np = 0; np < 2; ++np)
                    ldsm4t(bf[np], bb + (d0 + s1 + r8) * BP + (wn + np * 16 + s2) * 2);
                #pragma unroll
                for (int mf = 0; mf < 4; ++mf)
                    ldsm4t(af[mf], sb + SA + (d0 + s2 + r8) * AP + (wm + mf * 16 + s1) * 2);
                #pragma unroll
                for (int mf = 0; mf < 4; ++mf)
                    #pragma unroll
                    for (int nf = 0; nf < 4; ++nf)
                        mma16816(acc[mf][nf], af[mf], &bf[nf >> 1][(nf & 1) * 2]);
            }

            // epilogue: score = ||m||^2 - 2*dot, running min per row
            const int cb = c * 64 + wn + 2 * (ln & 3);
            #pragma unroll
            for (int nf = 0; nf < 4; ++nf) {
                float m0 = mns[cb + nf * 8], m1 = mns[cb + nf * 8 + 1];
                #pragma unroll
                for (int mf = 0; mf < 4; ++mf) {
                    rm[mf * 2]     = fminf(rm[mf * 2],
                        fminf(fmaf(-2.f, acc[mf][nf][0], m0), fmaf(-2.f, acc[mf][nf][1], m1)));
                    rm[mf * 2 + 1] = fminf(rm[mf * 2 + 1],
                        fminf(fmaf(-2.f, acc[mf][nf][2], m0), fmaf(-2.f, acc[mf][nf][3], m1)));
                }
            }
        }

        // combine 4 lanes sharing each row
        #pragma unroll
        for (int o = 1; o < 4; o <<= 1) {
            #pragma unroll
            for (int i = 0; i < 8; ++i) rm[i] = fminf(rm[i], __shfl_xor_sync(0xffffffffu, rm[i], o));
        }
        if ((ln & 3) == 0) {
            float* rmin = (float*)(sm + SRMIN) + (w >> 2) * 256;
            int r = wm + (ln >> 2);
            #pragma unroll
            for (int mf = 0; mf < 4; ++mf) {
                rmin[r + mf * 16]     = rm[mf * 2];
                rmin[r + mf * 16 + 8] = rm[mf * 2 + 1];
            }
        }
        __syncthreads();

        {   // combine n-groups, sum rows
            const float* r0 = (const float*)(sm + SRMIN);
            double s = (double)fminf(r0[tid], r0[tid + 256]);
            #pragma unroll
            for (int o = 16; o; o >>= 1) s += __shfl_down_sync(0xffffffffu, s, o);
            if (!ln) ((double*)(sm + SRED + 64))[w] = s;
        }
        __syncthreads();

        if (tid == 0) {
            const double* dr = (const double*)(sm + SRED + 64);
            double ms = 0.0;
            #pragma unroll
            for (int i = 0; i < 8; ++i) ms += dr[i];
            atomicAdd(&g_acc[1], ms);
            const float* ws = (const float*)(sm + SRED);
            double hs = 0.0;
            #pragma unroll
            for (int i = 0; i < 8; ++i) hs += (double)ws[i];
            atomicAdd(&g_acc[3], hs);
        }
    }

    // -------- shared ticketed finalize (all 148 CTAs) --------
    if (tid == 0) {
        __threadfence();
        unsigned old = atomicAdd(&g_ticket, 1u);
        if (old == gridDim.x - 1) {
            __threadfence();
            double a0 = *(volatile double*)&g_acc[0];
            double a1 = *(volatile double*)&g_acc[1];
            double a2 = *(volatile double*)&g_acc[2];
            double a3 = *(volatile double*)&g_acc[3];
            double mem = 2.0 * (a3 + a1) / (double)((size_t)Bn * Dn * Tn);
            out[0] = (float)(a0 / (double)N_REC + 0.25 * mem - 0.1 * a2 / (double)N_DHAT);
            g_acc[0] = 0.0; g_acc[1] = 0.0; g_acc[2] = 0.0; g_acc[3] = 0.0;
            g_ticket = 0u;
            __threadfence();
        }
    }
}

extern "C" void kernel_launch(void* const* d_in, const int* in_sizes, int n_in,
                              void* d_out, int out_size) {
    (void)in_sizes; (void)n_in; (void)out_size;
    const float* Xhat = (const float*)d_in[0];
    const float* X    = (const float*)d_in[1];
    const float* H    = (const float*)d_in[2];
    const float* M    = (const float*)d_in[3];
    const float* Dh   = (const float*)d_in[4];

    cudaFuncSetAttribute(k_mma, cudaFuncAttributeMaxDynamicSharedMemorySize, SMEMT);

    k_prep<<<16, 256>>>(M);
    k_mma<<<148, 256, SMEMT>>>(H, Xhat, X, Dh, (float*)d_out);
}

// round 14
// speedup vs baseline: 1.2960x; 1.0397x over previous
#include <cuda_runtime.h>
#include <cuda_bf16.h>
#include <cstdint>

// EDMLoss = mean((Xhat-X)^2) + 0.25*memloss - 0.1*mean(Dhat)
// memloss = 2*(sum||h||^2 + sum_row min_k(||m_k||^2 - 2 h.m_k)) / (B*D*T)
// SINGLE LAUNCH. 148 CTAs:
//   0..127  : GEMM CTAs (256 rows x 512 cols, mma.sync bf16 at the legacy-path
//             ceiling ~512 MAC/cyc/SM). A-stage first, then wait for M-ready.
//   128..143: convert M->bf16 + ||m||^2 (32 k-cols each), signal, then rec slices.
//   144..145: rec slices.   146..147: dhat slices.
// Ticketed finalize; all globals reset each run (graph-replay invariant).

namespace {
constexpr int Bn = 64, Dn = 256, Tn = 512, Kn = 512;
constexpr int N_REC  = 64 * 8 * 512;
constexpr int N_DHAT = 64 * 512;

constexpr uint32_t AP    = 528;                 // A pitch bytes (256 bf16 + 16 pad)
constexpr uint32_t BP    = 144;                 // B pitch bytes (64 bf16 + 16 pad)
constexpr uint32_t SA    = 0;                   // A: 256*528 = 135168
constexpr uint32_t SB0   = 135168;              // B buf0: 256*144 = 36864
constexpr uint32_t SB1   = 172032;              // B buf1
constexpr uint32_t SMNS  = 208896;              // 512 f32 ||m||^2
constexpr uint32_t SRMIN = 210944;              // 2 groups * 256 f32 row mins
constexpr uint32_t SRED  = 212992;              // 8 f32 | 8 doubles at +64
constexpr uint32_t SMEMT = 213120;
}

__device__ double g_acc[4];      // 0 rec, 1 minscore, 2 dhat, 3 sum H^2 (zero-invariant)
__device__ unsigned g_ticket;
__device__ unsigned g_mready;    // 16 converter CTAs arrive; reset by finalize
__device__ float  g_mnorm[Kn];
__device__ __align__(16) __nv_bfloat16 g_Mc[(size_t)Dn * Kn];

__device__ __forceinline__ uint32_t smem_u32(const void* p) {
    uint32_t a;
    asm("{ .reg .u64 t; cvta.to.shared.u64 t, %1; cvt.u32.u64 %0, t; }" : "=r"(a) : "l"(p));
    return a;
}
__device__ __forceinline__ void ldsm4t(uint32_t* r, uint32_t addr) {
    asm volatile("ldmatrix.sync.aligned.m8n8.x4.trans.shared.b16 {%0,%1,%2,%3}, [%4];"
                 : "=r"(r[0]), "=r"(r[1]), "=r"(r[2]), "=r"(r[3]) : "r"(addr));
}
__device__ __forceinline__ void mma16816(float* c, const uint32_t* a, const uint32_t* b) {
    asm volatile("mma.sync.aligned.m16n8k16.row.col.f32.bf16.bf16.f32 "
                 "{%0,%1,%2,%3}, {%4,%5,%6,%7}, {%8,%9}, {%0,%1,%2,%3};"
                 : "+f"(c[0]), "+f"(c[1]), "+f"(c[2]), "+f"(c[3])
                 : "r"(a[0]), "r"(a[1]), "r"(a[2]), "r"(a[3]), "r"(b[0]), "r"(b[1]));
}

__global__ __launch_bounds__(256, 1) void k_mma(const float* __restrict__ H,
                                                const float* __restrict__ M,
                                                const float* __restrict__ Xhat,
                                                const float* __restrict__ X,
                                                const float* __restrict__ Dh,
                                                float* out) {
    extern __shared__ char sm[];
    const uint32_t sb = smem_u32(sm);
    const int tid = threadIdx.x, w = tid >> 5, ln = tid & 31;

    if (blockIdx.x >= 128) {
        // -------- converter / reduction CTAs --------
        if (blockIdx.x < 144) {
            // convert 32 k-cols of M -> bf16, compute ||m||^2, signal ready
            __shared__ float part[8][32];
            const int kl = tid & 31, dg = tid >> 5;
            const int k  = ((int)blockIdx.x - 128) * 32 + kl;
            float s = 0.f;
            #pragma unroll 8
            for (int i = 0; i < 32; ++i) {
                int d = dg * 32 + i;
                float v = M[(size_t)d * Kn + k];
                g_Mc[(size_t)d * Kn + k] = __float2bfloat16(v);
                s = fmaf(v, v, s);
            }
            part[dg][kl] = s;
            __syncthreads();
            if (dg == 0) {
                float t = 0.f;
                #pragma unroll
                for (int i = 0; i < 8; ++i) t += part[i][kl];
                g_mnorm[k] = t;
            }
            __syncthreads();
            __threadfence();
            if (tid == 0) atomicAdd(&g_mready, 1u);
        }
        // rec / dhat slices
        int which, n, b0, nb;
        const float* a; const float* bp;
        if (blockIdx.x < 146) { which = 0; a = Xhat; bp = X; n = N_REC;  b0 = 128; nb = 18; }
        else                  { which = 2; a = Dh;   bp = 0; n = N_DHAT; b0 = 146; nb = 2;  }
        float s = 0.f;
        for (int i = ((int)blockIdx.x - b0) * 256 + tid; i < n; i += nb * 256) {
            if (which == 0) { float d = a[i] - bp[i]; s = fmaf(d, d, s); }
            else            { s += a[i]; }
        }
        #pragma unroll
        for (int o = 16; o; o >>= 1) s += __shfl_down_sync(0xffffffffu, s, o);
        float* ws = (float*)(sm + SRED);
        if (!ln) ws[w] = s;
        __syncthreads();
        if (tid == 0) {
            float t = 0.f;
            #pragma unroll
            for (int i = 0; i < 8; ++i) t += ws[i];
            atomicAdd(&g_acc[which], (double)t);
        }
    } else {
        // -------- GEMM CTA: 256 rows x 512 cols --------
        const int row0 = blockIdx.x * 256;
        const int b = row0 >> 9, t0 = row0 & 511;          // t0 in {0, 256}

        // Stage A FIRST (independent of M): H fp32 -> bf16 smem [d][t] + sum(H^2).
        float sq = 0.f;
        const float* Hp = H + (size_t)b * Dn * Tn + t0;
        #pragma unroll
        for (int i = 0; i < 64; ++i) {
            int u = tid + 256 * i;                 // 0..16383 float4 units
            int d = u >> 6, seg = u & 63;
            float4 v = *(const float4*)(Hp + (size_t)d * Tn + seg * 4);
            sq = fmaf(v.x, v.x, fmaf(v.y, v.y, fmaf(v.z, v.z, fmaf(v.w, v.w, sq))));
            __nv_bfloat162 p0 = __floats2bfloat162_rn(v.x, v.y);
            __nv_bfloat162 p1 = __floats2bfloat162_rn(v.z, v.w);
            uint32_t a = sb + SA + d * AP + seg * 8;
            asm volatile("st.shared.v2.b32 [%0], {%1,%2};"
                         :: "r"(a), "r"(*(uint32_t*)&p0), "r"(*(uint32_t*)&p1) : "memory");
        }
        #pragma unroll
        for (int o = 16; o; o >>= 1) sq += __shfl_down_sync(0xffffffffu, sq, o);
        if (!ln) ((float*)(sm + SRED))[w] = sq;
        __syncthreads();
        if (tid == 0) {
            const float* hws = (const float*)(sm + SRED);
            double hs = 0.0;
            #pragma unroll
            for (int i = 0; i < 8; ++i) hs += (double)hws[i];
            atomicAdd(&g_acc[3], hs);
            // wait for M conversion (usually done long ago: conversion ~1us vs A-stage ~5us)
            while (*((volatile unsigned*)&g_mready) < 16u) __nanosleep(64);
        }
        __syncthreads();
        __threadfence();

        ((float*)(sm + SMNS))[tid]       = g_mnorm[tid];
        ((float*)(sm + SMNS))[tid + 256] = g_mnorm[tid + 256];

        const size_t gmc = __cvta_generic_to_global((const void*)g_Mc);
        auto cp_chunk = [&](int c, uint32_t dstoff) {       // 64-col chunk: 256 rows * 128B
            #pragma unroll
            for (int i = 0; i < 8; ++i) {
                int u = tid + 256 * i;                      // 0..2047 16B units
                int d = u >> 3, seg = u & 7;
                uint32_t dst = sb + dstoff + d * BP + seg * 16;
                size_t   src = gmc + (size_t)d * 1024 + (size_t)c * 128 + seg * 16;
                asm volatile("cp.async.cg.shared.global [%0], [%1], 16;" :: "r"(dst), "l"(src));
            }
            asm volatile("cp.async.commit_group;" ::: "memory");
        };
        cp_chunk(0, SB0);
        cp_chunk(1, SB1);

        // 8 warps: 4 (m) x 2 (n). Warp tile per chunk: 64 rows x 32 cols.
        const int wm  = (w & 3) * 64;
        const int wn  = (w >> 2) * 32;
        const int s1  = ((ln >> 3) & 1) * 8;
        const int s2  = (ln >> 4) * 8;
        const int r8  = ln & 7;
        const float* mns = (const float*)(sm + SMNS);

        float rm[8];
        #pragma unroll
        for (int i = 0; i < 8; ++i) rm[i] = 3.4e38f;

        // Single barrier per chunk: sync proves chunk c arrived AND chunk c-1
        // consumers finished -> buffer (c+1)&1 free; prefetch immediately.
        for (int c = 0; c < 8; ++c) {
            if (c == 0) asm volatile("cp.async.wait_group 1;" ::: "memory");
            else        asm volatile("cp.async.wait_group 0;" ::: "memory");
            __syncthreads();
            if (c >= 1 && c + 1 < 8) cp_chunk(c + 1, ((c + 1) & 1) ? SB1 : SB0);
            const uint32_t bb = sb + ((c & 1) ? SB1 : SB0);

            float acc[4][4][4];
            #pragma unroll
            for (int mf = 0; mf < 4; ++mf)
                #pragma unroll
                for (int nf = 0; nf < 4; ++nf)
                    #pragma unroll
                    for (int j = 0; j < 4; ++j) acc[mf][nf][j] = 0.f;

            #pragma unroll
            for (int ks = 0; ks < 16; ++ks) {
                const int d0 = ks * 16;
                uint32_t af[4][4], bf[2][4];
                #pragma unroll
                for (int np = 0; np < 2; ++np)
                    ldsm4t(bf[np], bb + (d0 + s1 + r8) * BP + (wn + np * 16 + s2) * 2);
                #pragma unroll
                for (int mf = 0; mf < 4; ++mf)
                    ldsm4t(af[mf], sb + SA + (d0 + s2 + r8) * AP + (wm + mf * 16 + s1) * 2);
                #pragma unroll
                for (int mf = 0; mf < 4; ++mf)
                    #pragma unroll
                    for (int nf = 0; nf < 4; ++nf)
                        mma16816(acc[mf][nf], af[mf], &bf[nf >> 1][(nf & 1) * 2]);
            }

            // epilogue: score = ||m||^2 - 2*dot, running min per row
            const int cb = c * 64 + wn + 2 * (ln & 3);
            #pragma unroll
            for (int nf = 0; nf < 4; ++nf) {
                float m0 = mns[cb + nf * 8], m1 = mns[cb + nf * 8 + 1];
                #pragma unroll
                for (int mf = 0; mf < 4; ++mf) {
                    rm[mf * 2]     = fminf(rm[mf * 2],
                        fminf(fmaf(-2.f, acc[mf][nf][0], m0), fmaf(-2.f, acc[mf][nf][1], m1)));
                    rm[mf * 2 + 1] = fminf(rm[mf * 2 + 1],
                        fminf(fmaf(-2.f, acc[mf][nf][2], m0), fmaf(-2.f, acc[mf][nf][3], m1)));
                }
            }
        }

        // combine 4 lanes sharing each row
        #pragma unroll
        for (int o = 1; o < 4; o <<= 1) {
            #pragma unroll
            for (int i = 0; i < 8; ++i) rm[i] = fminf(rm[i], __shfl_xor_sync(0xffffffffu, rm[i], o));
        }
        if ((ln & 3) == 0) {
            float* rmin = (float*)(sm + SRMIN) + (w >> 2) * 256;
            int r = wm + (ln >> 2);
            #pragma unroll
            for (int mf = 0; mf < 4; ++mf) {
                rmin[r + mf * 16]     = rm[mf * 2];
                rmin[r + mf * 16 + 8] = rm[mf * 2 + 1];
            }
        }
        __syncthreads();

        {   // combine n-groups, sum rows
            const float* r0 = (const float*)(sm + SRMIN);
            double s = (double)fminf(r0[tid], r0[tid + 256]);
            #pragma unroll
            for (int o = 16; o; o >>= 1) s += __shfl_down_sync(0xffffffffu, s, o);
            if (!ln) ((double*)(sm + SRED + 64))[w] = s;
        }
        __syncthreads();

        if (tid == 0) {
            const double* dr = (const double*)(sm + SRED + 64);
            double ms = 0.0;
            #pragma unroll
            for (int i = 0; i < 8; ++i) ms += dr[i];
            atomicAdd(&g_acc[1], ms);
        }
    }

    // -------- shared ticketed finalize (all 148 CTAs) --------
    if (tid == 0) {
        __threadfence();
        unsigned old = atomicAdd(&g_ticket, 1u);
        if (old == gridDim.x - 1) {
            __threadfence();
            double a0 = *(volatile double*)&g_acc[0];
            double a1 = *(volatile double*)&g_acc[1];
            double a2 = *(volatile double*)&g_acc[2];
            double a3 = *(volatile double*)&g_acc[3];
            double mem = 2.0 * (a3 + a1) / (double)((size_t)Bn * Dn * Tn);
            out[0] = (float)(a0 / (double)N_REC + 0.25 * mem - 0.1 * a2 / (double)N_DHAT);
            g_acc[0] = 0.0; g_acc[1] = 0.0; g_acc[2] = 0.0; g_acc[3] = 0.0;
            g_ticket = 0u; g_mready = 0u;
            __threadfence();
        }
    }
}

extern "C" void kernel_launch(void* const* d_in, const int* in_sizes, int n_in,
                              void* d_out, int out_size) {
    (void)in_sizes; (void)n_in; (void)out_size;
    const float* Xhat = (const float*)d_in[0];
    const float* X    = (const float*)d_in[1];
    const float* H    = (const float*)d_in[2];
    const float* M    = (const float*)d_in[3];
    const float* Dh   = (const float*)d_in[4];

    cudaFuncSetAttribute(k_mma, cudaFuncAttributeMaxDynamicSharedMemorySize, SMEMT);

    k_mma<<<148, 256, SMEMT>>>(H, M, Xhat, X, Dh, (float*)d_out);
}